// round 15
// baseline (speedup 1.0000x reference)
#include <cuda_runtime.h>
#include <cuda_fp16.h>

// RGCN constants
constexpr int N_   = 50000;
constexpr int E_   = 500000;
constexpr int R_   = 20;
constexpr int RT_  = 41;            // 2R+1
constexpr int B_   = 40;
constexpr int EMB_ = 16;
constexpr int C_   = 16;
constexpr int NE_  = N_ * EMB_;     // 800000
constexpr int RC_  = RT_ * C_;      // 656
constexpr int NTILES_ = N_ / 16;    // 3125 node tiles
constexpr int NT_  = 4;             // node tiles per block in mgemm
constexpr int JT_  = 512;           // j columns per w1 block
constexpr int WGB_ = (NE_ + JT_ - 1) / JT_;   // 1563 GEMM blocks
constexpr int CNTB_ = 128;          // fused counting blocks (grid-stride)

// dynamic smem layout for k_w1t
constexpr int SMA_OFF = 0;                    // comps fp16 [48][48]
constexpr int SMB_OFF = 4608;                 // bases fp16 [512][50]
constexpr int SMO_OFF = 4608 + 51200;         // out fp16 [48][520]
constexpr int SMEM_W1 = SMO_OFF + 48 * 520 * 2;   // 105728 B

// Scratch (static device globals) — big tensors stored fp16
__device__ __half g_w1h[(size_t)RT_ * NE_];  // [41][50000][16]  65.6 MB
__device__ float  g_h[NE_];                  // layer-1 edge-sum (fp32)
__device__ int    g_cnt[RT_ * N_];           // per-(r,s) edge counts
__device__ __half g_w2h[EMB_ * RC_];         // w2 flat [e][r*16+c], fp16
__device__ __half g_mh[(size_t)N_ * RC_];    // m[o][r][c]  65.6 MB

static __device__ __forceinline__ unsigned smem_u32(const void* p) {
    unsigned a;
    asm("{ .reg .u64 t; cvta.to.shared.u64 t, %1; cvt.u32.u64 %0, t; }"
        : "=r"(a) : "l"(p));
    return a;
}

// ---------------------------------------------------------------------------
// pre-pass: zero cnt & h, seed out with bias2, compute w2 (fp16). One launch.
__global__ void k_pre(float* __restrict__ out, const float* __restrict__ bias2,
                      const float* __restrict__ comps2,
                      const float* __restrict__ bases2) {
    int i = blockIdx.x * blockDim.x + threadIdx.x;
    if (i < RT_ * N_) g_cnt[i] = 0;
    if (i < NE_) { g_h[i] = 0.0f; out[i] = bias2[i & 15]; }
    if (i < RT_ * EMB_ * C_) {
        int r = i >> 8, ec = i & 255;
        int e = ec >> 4, c = ec & 15;
        float acc = 0.0f;
#pragma unroll
        for (int b = 0; b < B_; b++)
            acc = fmaf(comps2[r * B_ + b], bases2[b * 256 + ec], acc);
        g_w2h[e * RC_ + r * 16 + c] = __float2half_rn(acc);
    }
}

// ---------------------------------------------------------------------------
// Tensor-core w1 GEMM (+ fused edge counting in trailing blocks).
// w1[r][j] = sum_b comps1[r][b] * bases1[b][j]; M=41(pad 48), K=40(pad 48),
// 512 j per block. A (comps) in registers (9 fragments); bases staged
// transposed [j][b] fp16; output staged [48][520] then row-copied out.
__global__ void __launch_bounds__(128) k_w1t(const float* __restrict__ comps1,
                                             const float* __restrict__ bases1,
                                             const int* __restrict__ src,
                                             const int* __restrict__ dst,
                                             const int* __restrict__ rel) {
    if (blockIdx.x >= WGB_) {                 // edge counting, grid-stride
        for (int i = (blockIdx.x - WGB_) * 128 + threadIdx.x; i < E_;
             i += CNTB_ * 128) {
            int r = rel[i];
            atomicAdd(&g_cnt[r * N_ + src[i]], 1);
            atomicAdd(&g_cnt[(r + R_) * N_ + dst[i]], 1);
        }
        return;
    }

    extern __shared__ __align__(16) char smem[];
    __half* smA = (__half*)(smem + SMA_OFF);  // [48][48]
    __half* smB = (__half*)(smem + SMB_OFF);  // [512][50]
    __half* smO = (__half*)(smem + SMO_OFF);  // [48][520]

    int tid = threadIdx.x, lane = tid & 31, w = tid >> 5;

    // stage comps fp16, zero-padded to 48x48
    for (int i = tid; i < 48 * 48; i += 128) {
        int r = i / 48, k = i % 48;
        float v = (r < RT_ && k < B_) ? comps1[r * B_ + k] : 0.0f;
        smA[i] = __float2half_rn(v);
    }

    // stage bases transposed [j][b] fp16 (cols 40..47 zeroed); row=50 halves
    int jbase = blockIdx.x * JT_;
#pragma unroll 1
    for (int b = 0; b < 48; b += 2) {
#pragma unroll
        for (int k = 0; k < 4; k++) {
            int jo = tid + k * 128;
            int j = jbase + jo;
            float v0 = 0.0f, v1 = 0.0f;
            if (b < B_ && j < NE_) {
                v0 = bases1[(size_t)b * NE_ + j];
                v1 = bases1[(size_t)(b + 1) * NE_ + j];
            }
            *(__half2*)&smB[jo * 50 + b] = __floats2half2_rn(v0, v1);
        }
    }
    __syncthreads();

    // load 9 A fragments (M-tiles x K-steps)
    unsigned af[3][3][4];
    unsigned sa = smem_u32(smA);
#pragma unroll
    for (int m = 0; m < 3; m++)
#pragma unroll
        for (int s = 0; s < 3; s++) {
            unsigned addr = sa + (m * 16 + (lane & 15)) * 96 + s * 32 + (lane >> 4) * 16;
            asm("ldmatrix.sync.aligned.m8n8.x4.shared.b16 {%0,%1,%2,%3}, [%4];"
                : "=r"(af[m][s][0]), "=r"(af[m][s][1]),
                  "=r"(af[m][s][2]), "=r"(af[m][s][3]) : "r"(addr));
        }

    int k0   = (lane & 3) * 2;
    int nIdx = lane >> 2;                // j within group / output row quarter
    int colq = (lane & 3) * 2;

    // 16 j-groups of 8 per warp
#pragma unroll 1
    for (int g = 0; g < 16; g++) {
        int jg = w * 128 + g * 8;
        float d[3][4];
#pragma unroll
        for (int m = 0; m < 3; m++)
            d[m][0] = d[m][1] = d[m][2] = d[m][3] = 0.0f;
#pragma unroll
        for (int s = 0; s < 3; s++) {
            const __half* bp = &smB[(jg + nIdx) * 50 + s * 16 + k0];
            unsigned bf0 = *(const unsigned*)bp;
            unsigned bf1 = *(const unsigned*)(bp + 8);
#pragma unroll
            for (int m = 0; m < 3; m++) {
                asm("mma.sync.aligned.m16n8k16.row.col.f32.f16.f16.f32 "
                    "{%0,%1,%2,%3}, {%4,%5,%6,%7}, {%8,%9}, {%0,%1,%2,%3};"
                    : "+f"(d[m][0]), "+f"(d[m][1]), "+f"(d[m][2]), "+f"(d[m][3])
                    : "r"(af[m][s][0]), "r"(af[m][s][1]),
                      "r"(af[m][s][2]), "r"(af[m][s][3]), "r"(bf0), "r"(bf1));
            }
        }
#pragma unroll
        for (int m = 0; m < 3; m++) {
            unsigned s0, s1;
            asm("cvt.rn.f16x2.f32 %0, %1, %2;" : "=r"(s0) : "f"(d[m][1]), "f"(d[m][0]));
            asm("cvt.rn.f16x2.f32 %0, %1, %2;" : "=r"(s1) : "f"(d[m][3]), "f"(d[m][2]));
            *(unsigned*)&smO[(m * 16 + nIdx) * 520 + jg + colq] = s0;
            *(unsigned*)&smO[(m * 16 + nIdx + 8) * 520 + jg + colq] = s1;
        }
    }
    __syncthreads();

    // copy rows 0..40 (512 halves each, contiguous in g_w1h) out
    for (int i = tid; i < RT_ * (JT_ / 8); i += 128) {
        int r = i >> 6, c8 = i & 63;
        int j = jbase + c8 * 8;
        if (j < NE_)
            *(uint4*)&g_w1h[(size_t)r * NE_ + j] = *(const uint4*)&smO[r * 520 + c8 * 8];
    }
}

// ---------------------------------------------------------------------------
// layer-1 scatter: h[s,:] += v * w1[r, o, :].  4 lanes/edge, fp16 gather,
// one fp32 RED.v4.
__global__ void k_l1(const int* __restrict__ src, const int* __restrict__ dst,
                     const int* __restrict__ rel) {
    int idx = blockIdx.x * blockDim.x + threadIdx.x;
    if (idx >= 2 * E_ * 4) return;
    int q  = idx & 3;
    int e2 = idx >> 2;
    int s, o, r;
    if (e2 < E_) { s = src[e2]; o = dst[e2]; r = rel[e2]; }
    else         { int e = e2 - E_; s = dst[e]; o = src[e]; r = rel[e] + R_; }
    float v = 1.0f / (float)g_cnt[r * N_ + s];
    const uint2 hw = *(const uint2*)&g_w1h[(size_t)r * NE_ + o * EMB_ + q * 4];
    float2 f01 = __half22float2(*(const __half2*)&hw.x);
    float2 f23 = __half22float2(*(const __half2*)&hw.y);
    float* hp = &g_h[s * EMB_ + q * 4];
    asm volatile("red.global.add.v4.f32 [%0], {%1, %2, %3, %4};"
                 :: "l"(hp), "f"(v * f01.x), "f"(v * f01.y),
                    "f"(v * f23.x), "f"(v * f23.y)
                 : "memory");
}

// ---------------------------------------------------------------------------
// Tensor-core m-GEMM with smem-staged epilogue (unchanged from round 14).
__global__ void __launch_bounds__(128) k_mgemm(const float* __restrict__ bias1) {
    __shared__ __half sA[256];
    __shared__ __align__(16) __half sOut[16 * RC_];
    int tid  = threadIdx.x;
    int lane = tid & 31;
    int w    = tid >> 5;

    int nOwn = (w < 2) ? 21 : 20;
    int k0   = (lane & 3) * 2;
    int nIdx = lane >> 2;
    unsigned bf0[21], bf1[21];
#pragma unroll
    for (int t = 0; t < 21; t++) {
        if (t < nOwn) {
            int n = (w + 4 * t) * 8 + nIdx;
            __half2 lo = __halves2half2(g_w2h[k0 * RC_ + n], g_w2h[(k0 + 1) * RC_ + n]);
            __half2 hi = __halves2half2(g_w2h[(k0 + 8) * RC_ + n], g_w2h[(k0 + 9) * RC_ + n]);
            bf0[t] = *(unsigned*)&lo;
            bf1[t] = *(unsigned*)&hi;
        }
    }

    const __half* w1sl = &g_w1h[(size_t)(RT_ - 1) * NE_];
    unsigned abase = smem_u32(sA) + (lane & 15) * 32 + (lane >> 4) * 16;
    int rowq = lane >> 2;
    int colq = (lane & 3) * 2;

    int tile0 = blockIdx.x * NT_;
#pragma unroll 1
    for (int tt = 0; tt < NT_; tt++) {
        int gt = tile0 + tt;
        if (gt >= NTILES_) break;

        for (int i = tid; i < 256; i += 128) {
            int node = gt * 16 + (i >> 4);
            int e = i & 15;
            float x = fmaxf(g_h[node * EMB_ + e]
                            + __half2float(w1sl[node * EMB_ + e]) + bias1[e], 0.0f);
            sA[i] = __float2half_rn(x);
        }
        __syncthreads();

        unsigned a0, a1, a2, a3;
        asm("ldmatrix.sync.aligned.m8n8.x4.shared.b16 {%0,%1,%2,%3}, [%4];"
            : "=r"(a0), "=r"(a1), "=r"(a2), "=r"(a3) : "r"(abase));
#pragma unroll
        for (int t = 0; t < 21; t++) {
            if (t >= nOwn) break;
            float d0, d1, d2, d3;
            asm("mma.sync.aligned.m16n8k16.row.col.f32.f16.f16.f32 "
                "{%0,%1,%2,%3}, {%4,%5,%6,%7}, {%8,%9}, {%10,%11,%12,%13};"
                : "=f"(d0), "=f"(d1), "=f"(d2), "=f"(d3)
                : "r"(a0), "r"(a1), "r"(a2), "r"(a3), "r"(bf0[t]), "r"(bf1[t]),
                  "f"(0.0f), "f"(0.0f), "f"(0.0f), "f"(0.0f));
            unsigned s0, s1;
            asm("cvt.rn.f16x2.f32 %0, %1, %2;" : "=r"(s0) : "f"(d1), "f"(d0));
            asm("cvt.rn.f16x2.f32 %0, %1, %2;" : "=r"(s1) : "f"(d3), "f"(d2));
            int col = (w + 4 * t) * 8 + colq;
            *(unsigned*)&sOut[rowq * RC_ + col] = s0;
            *(unsigned*)&sOut[(rowq + 8) * RC_ + col] = s1;
        }
        __syncthreads();

        uint4* dst4 = (uint4*)&g_mh[(size_t)gt * 16 * RC_];
        const uint4* src4 = (const uint4*)sOut;
        for (int i = tid; i < 16 * RC_ / 8; i += 128)
            dst4[i] = src4[i];
        __syncthreads();
    }
}

// ---------------------------------------------------------------------------
// layer-2 edge pass incl. self-loop pseudo-edges: out[s,:] += v * m[o][r][:]
__global__ void k_l2e(const int* __restrict__ src, const int* __restrict__ dst,
                      const int* __restrict__ rel, float* __restrict__ out) {
    int idx = blockIdx.x * blockDim.x + threadIdx.x;
    if (idx >= (2 * E_ + N_) * 4) return;
    int q  = idx & 3;
    int e2 = idx >> 2;
    int s, o, r;
    float v;
    if (e2 < E_) {
        s = src[e2]; o = dst[e2]; r = rel[e2];
        v = 1.0f / (float)g_cnt[r * N_ + s];
    } else if (e2 < 2 * E_) {
        int e = e2 - E_;
        s = dst[e]; o = src[e]; r = rel[e] + R_;
        v = 1.0f / (float)g_cnt[r * N_ + s];
    } else {
        int n = e2 - 2 * E_;
        s = n; o = n; r = RT_ - 1; v = 1.0f;
    }
    const uint2 mw = *(const uint2*)&g_mh[(size_t)o * RC_ + r * 16 + q * 4];
    float2 f01 = __half22float2(*(const __half2*)&mw.x);
    float2 f23 = __half22float2(*(const __half2*)&mw.y);
    float* op = &out[s * C_ + q * 4];
    asm volatile("red.global.add.v4.f32 [%0], {%1, %2, %3, %4};"
                 :: "l"(op), "f"(v * f01.x), "f"(v * f01.y),
                    "f"(v * f23.x), "f"(v * f23.y)
                 : "memory");
}

// ---------------------------------------------------------------------------
extern "C" void kernel_launch(void* const* d_in, const int* in_sizes, int n_in,
                              void* d_out, int out_size) {
    const int*   src    = (const int*)d_in[0];
    const int*   dst    = (const int*)d_in[1];
    const int*   rel    = (const int*)d_in[2];
    const float* comps1 = (const float*)d_in[3];
    const float* bases1 = (const float*)d_in[4];
    const float* comps2 = (const float*)d_in[5];
    const float* bases2 = (const float*)d_in[6];
    const float* bias1  = (const float*)d_in[7];
    const float* bias2  = (const float*)d_in[8];
    float* out = (float*)d_out;

    static bool attr_set = false;
    if (!attr_set) {
        cudaFuncSetAttribute(k_w1t, cudaFuncAttributeMaxDynamicSharedMemorySize,
                             SMEM_W1);
        attr_set = true;
    }

    const int T = 256;
    k_pre   <<<(RT_ * N_ + T - 1) / T, T>>>(out, bias2, comps2, bases2);
    k_w1t   <<<WGB_ + CNTB_, 128, SMEM_W1>>>(comps1, bases1, src, dst, rel);
    k_l1    <<<(2 * E_ * 4 + T - 1) / T, T>>>(src, dst, rel);
    k_mgemm <<<(NTILES_ + NT_ - 1) / NT_, 128>>>(bias1);
    k_l2e   <<<((2 * E_ + N_) * 4 + T - 1) / T, T>>>(src, dst, rel, out);
}

// round 16
// speedup vs baseline: 1.5253x; 1.5253x over previous
#include <cuda_runtime.h>
#include <cuda_fp16.h>

// RGCN constants
constexpr int N_   = 50000;
constexpr int E_   = 500000;
constexpr int R_   = 20;
constexpr int RT_  = 41;            // 2R+1
constexpr int B_   = 40;
constexpr int EMB_ = 16;
constexpr int C_   = 16;
constexpr int NE_  = N_ * EMB_;     // 800000
constexpr int RC_  = RT_ * C_;      // 656
constexpr int NTILES_ = N_ / 16;    // 3125 node tiles
constexpr int NT_  = 4;             // node tiles per block in mgemm
constexpr int JT_  = 256;           // j columns per w1 block
constexpr int WGB_ = NE_ / JT_;     // 3125 GEMM blocks (exact)
constexpr int CB2_ = (E_ + 255) / 256;  // 1954 one-shot counting blocks

// dynamic smem layout for k_w1t (55.5 KB -> 2 blocks/SM)
constexpr int SMA_OFF = 0;                    // comps fp16 [48][48]   4608 B
constexpr int SMB_OFF = 4608;                 // bases fp16 [256][50] 25600 B
constexpr int SMO_OFF = 4608 + 25600;         // out fp16 [48][264]   25344 B
constexpr int SMEM_W1 = SMO_OFF + 48 * 264 * 2;   // 55552 B

// Scratch (static device globals) — big tensors stored fp16
__device__ __half g_w1h[(size_t)RT_ * NE_];  // [41][50000][16]  65.6 MB
__device__ float  g_h[NE_];                  // layer-1 edge-sum (fp32)
__device__ int    g_cnt[RT_ * N_];           // per-(r,s) edge counts
__device__ __half g_w2h[EMB_ * RC_];         // w2 flat [e][r*16+c], fp16
__device__ __half g_mh[(size_t)N_ * RC_];    // m[o][r][c]  65.6 MB

static __device__ __forceinline__ unsigned smem_u32(const void* p) {
    unsigned a;
    asm("{ .reg .u64 t; cvta.to.shared.u64 t, %1; cvt.u32.u64 %0, t; }"
        : "=r"(a) : "l"(p));
    return a;
}

// ---------------------------------------------------------------------------
// pre-pass: zero cnt & h, seed out with bias2, compute w2 (fp16). One launch.
__global__ void k_pre(float* __restrict__ out, const float* __restrict__ bias2,
                      const float* __restrict__ comps2,
                      const float* __restrict__ bases2) {
    int i = blockIdx.x * blockDim.x + threadIdx.x;
    if (i < RT_ * N_) g_cnt[i] = 0;
    if (i < NE_) { g_h[i] = 0.0f; out[i] = bias2[i & 15]; }
    if (i < RT_ * EMB_ * C_) {
        int r = i >> 8, ec = i & 255;
        int e = ec >> 4, c = ec & 15;
        float acc = 0.0f;
#pragma unroll
        for (int b = 0; b < B_; b++)
            acc = fmaf(comps2[r * B_ + b], bases2[b * 256 + ec], acc);
        g_w2h[e * RC_ + r * 16 + c] = __float2half_rn(acc);
    }
}

// ---------------------------------------------------------------------------
// Tensor-core w1 GEMM, v2: 256 thr, 256 j/block, 55.5KB smem (2 blocks/SM).
// w1[r][j] = sum_b comps1[r][b]*bases1[b][j]; M=41(pad48), K=40(pad48).
// Trailing blocks do one-shot edge counting (restored from round 14).
__global__ void __launch_bounds__(256) k_w1t(const float* __restrict__ comps1,
                                             const float* __restrict__ bases1,
                                             const int* __restrict__ src,
                                             const int* __restrict__ dst,
                                             const int* __restrict__ rel) {
    if (blockIdx.x >= WGB_) {                 // one-shot edge counting
        int i = (blockIdx.x - WGB_) * 256 + threadIdx.x;
        if (i < E_) {
            int r = rel[i];
            atomicAdd(&g_cnt[r * N_ + src[i]], 1);
            atomicAdd(&g_cnt[(r + R_) * N_ + dst[i]], 1);
        }
        return;
    }

    extern __shared__ __align__(16) char smem[];
    __half* smA = (__half*)(smem + SMA_OFF);  // [48][48]
    __half* smB = (__half*)(smem + SMB_OFF);  // [256][50]
    __half* smO = (__half*)(smem + SMO_OFF);  // [48][264]

    int tid = threadIdx.x, lane = tid & 31, w = tid >> 5;
    int jbase = blockIdx.x * JT_;

    // stage comps fp16, zero-padded to 48x48
    for (int i = tid; i < 48 * 48; i += 256) {
        int r = i / 48, k = i % 48;
        float v = (r < RT_ && k < B_) ? comps1[r * B_ + k] : 0.0f;
        smA[i] = __float2half_rn(v);
    }

    // stage bases transposed: thread t owns column j = jbase+t (no bounds
    // checks: NE_ = 3125*256). Row stride 50 halves -> conflict-free.
    {
        int j = jbase + tid;
#pragma unroll
        for (int k = 0; k < 20; k++) {
            float v0 = bases1[(size_t)(2 * k) * NE_ + j];
            float v1 = bases1[(size_t)(2 * k + 1) * NE_ + j];
            *(__half2*)&smB[tid * 50 + 2 * k] = __floats2half2_rn(v0, v1);
        }
        __half2 z = __floats2half2_rn(0.0f, 0.0f);
#pragma unroll
        for (int k = 20; k < 24; k++)
            *(__half2*)&smB[tid * 50 + 2 * k] = z;   // K-pad 40..47
    }
    __syncthreads();

    // 9 A fragments (3 M-tiles x 3 K-steps) — addressing verified in r15
    unsigned af[3][3][4];
    unsigned sa = smem_u32(smA);
#pragma unroll
    for (int m = 0; m < 3; m++)
#pragma unroll
        for (int s = 0; s < 3; s++) {
            unsigned addr = sa + (m * 16 + (lane & 15)) * 96 + s * 32 + (lane >> 4) * 16;
            asm("ldmatrix.sync.aligned.m8n8.x4.shared.b16 {%0,%1,%2,%3}, [%4];"
                : "=r"(af[m][s][0]), "=r"(af[m][s][1]),
                  "=r"(af[m][s][2]), "=r"(af[m][s][3]) : "r"(addr));
        }

    int k0   = (lane & 3) * 2;
    int nIdx = lane >> 2;
    int colq = (lane & 3) * 2;

    // 4 j-groups of 8 per warp (8 warps x 32 j = 256)
#pragma unroll
    for (int g = 0; g < 4; g++) {
        int jg = w * 32 + g * 8;
        float d[3][4];
#pragma unroll
        for (int m = 0; m < 3; m++)
            d[m][0] = d[m][1] = d[m][2] = d[m][3] = 0.0f;
#pragma unroll
        for (int s = 0; s < 3; s++) {
            const __half* bp = &smB[(jg + nIdx) * 50 + s * 16 + k0];
            unsigned bf0 = *(const unsigned*)bp;
            unsigned bf1 = *(const unsigned*)(bp + 8);
#pragma unroll
            for (int m = 0; m < 3; m++) {
                asm("mma.sync.aligned.m16n8k16.row.col.f32.f16.f16.f32 "
                    "{%0,%1,%2,%3}, {%4,%5,%6,%7}, {%8,%9}, {%0,%1,%2,%3};"
                    : "+f"(d[m][0]), "+f"(d[m][1]), "+f"(d[m][2]), "+f"(d[m][3])
                    : "r"(af[m][s][0]), "r"(af[m][s][1]),
                      "r"(af[m][s][2]), "r"(af[m][s][3]), "r"(bf0), "r"(bf1));
            }
        }
#pragma unroll
        for (int m = 0; m < 3; m++) {
            unsigned s0, s1;
            asm("cvt.rn.f16x2.f32 %0, %1, %2;" : "=r"(s0) : "f"(d[m][1]), "f"(d[m][0]));
            asm("cvt.rn.f16x2.f32 %0, %1, %2;" : "=r"(s1) : "f"(d[m][3]), "f"(d[m][2]));
            *(unsigned*)&smO[(m * 16 + nIdx) * 264 + jg + colq] = s0;
            *(unsigned*)&smO[(m * 16 + nIdx + 8) * 264 + jg + colq] = s1;
        }
    }
    __syncthreads();

    // copy rows 0..40 (256 halves each, contiguous in g_w1h)
    for (int i = tid; i < RT_ * (JT_ / 8); i += 256) {
        int r = i >> 5, c8 = i & 31;
        *(uint4*)&g_w1h[(size_t)r * NE_ + jbase + c8 * 8] =
            *(const uint4*)&smO[r * 264 + c8 * 8];
    }
}

// ---------------------------------------------------------------------------
// layer-1 scatter: h[s,:] += v * w1[r, o, :].  4 lanes/edge, fp16 gather,
// one fp32 RED.v4.
__global__ void k_l1(const int* __restrict__ src, const int* __restrict__ dst,
                     const int* __restrict__ rel) {
    int idx = blockIdx.x * blockDim.x + threadIdx.x;
    if (idx >= 2 * E_ * 4) return;
    int q  = idx & 3;
    int e2 = idx >> 2;
    int s, o, r;
    if (e2 < E_) { s = src[e2]; o = dst[e2]; r = rel[e2]; }
    else         { int e = e2 - E_; s = dst[e]; o = src[e]; r = rel[e] + R_; }
    float v = 1.0f / (float)g_cnt[r * N_ + s];
    const uint2 hw = *(const uint2*)&g_w1h[(size_t)r * NE_ + o * EMB_ + q * 4];
    float2 f01 = __half22float2(*(const __half2*)&hw.x);
    float2 f23 = __half22float2(*(const __half2*)&hw.y);
    float* hp = &g_h[s * EMB_ + q * 4];
    asm volatile("red.global.add.v4.f32 [%0], {%1, %2, %3, %4};"
                 :: "l"(hp), "f"(v * f01.x), "f"(v * f01.y),
                    "f"(v * f23.x), "f"(v * f23.y)
                 : "memory");
}

// ---------------------------------------------------------------------------
// Tensor-core m-GEMM with smem-staged epilogue (round-14, unchanged).
__global__ void __launch_bounds__(128) k_mgemm(const float* __restrict__ bias1) {
    __shared__ __half sA[256];
    __shared__ __align__(16) __half sOut[16 * RC_];
    int tid  = threadIdx.x;
    int lane = tid & 31;
    int w    = tid >> 5;

    int nOwn = (w < 2) ? 21 : 20;
    int k0   = (lane & 3) * 2;
    int nIdx = lane >> 2;
    unsigned bf0[21], bf1[21];
#pragma unroll
    for (int t = 0; t < 21; t++) {
        if (t < nOwn) {
            int n = (w + 4 * t) * 8 + nIdx;
            __half2 lo = __halves2half2(g_w2h[k0 * RC_ + n], g_w2h[(k0 + 1) * RC_ + n]);
            __half2 hi = __halves2half2(g_w2h[(k0 + 8) * RC_ + n], g_w2h[(k0 + 9) * RC_ + n]);
            bf0[t] = *(unsigned*)&lo;
            bf1[t] = *(unsigned*)&hi;
        }
    }

    const __half* w1sl = &g_w1h[(size_t)(RT_ - 1) * NE_];
    unsigned abase = smem_u32(sA) + (lane & 15) * 32 + (lane >> 4) * 16;
    int rowq = lane >> 2;
    int colq = (lane & 3) * 2;

    int tile0 = blockIdx.x * NT_;
#pragma unroll 1
    for (int tt = 0; tt < NT_; tt++) {
        int gt = tile0 + tt;
        if (gt >= NTILES_) break;

        for (int i = tid; i < 256; i += 128) {
            int node = gt * 16 + (i >> 4);
            int e = i & 15;
            float x = fmaxf(g_h[node * EMB_ + e]
                            + __half2float(w1sl[node * EMB_ + e]) + bias1[e], 0.0f);
            sA[i] = __float2half_rn(x);
        }
        __syncthreads();

        unsigned a0, a1, a2, a3;
        asm("ldmatrix.sync.aligned.m8n8.x4.shared.b16 {%0,%1,%2,%3}, [%4];"
            : "=r"(a0), "=r"(a1), "=r"(a2), "=r"(a3) : "r"(abase));
#pragma unroll
        for (int t = 0; t < 21; t++) {
            if (t >= nOwn) break;
            float d0, d1, d2, d3;
            asm("mma.sync.aligned.m16n8k16.row.col.f32.f16.f16.f32 "
                "{%0,%1,%2,%3}, {%4,%5,%6,%7}, {%8,%9}, {%10,%11,%12,%13};"
                : "=f"(d0), "=f"(d1), "=f"(d2), "=f"(d3)
                : "r"(a0), "r"(a1), "r"(a2), "r"(a3), "r"(bf0[t]), "r"(bf1[t]),
                  "f"(0.0f), "f"(0.0f), "f"(0.0f), "f"(0.0f));
            unsigned s0, s1;
            asm("cvt.rn.f16x2.f32 %0, %1, %2;" : "=r"(s0) : "f"(d1), "f"(d0));
            asm("cvt.rn.f16x2.f32 %0, %1, %2;" : "=r"(s1) : "f"(d3), "f"(d2));
            int col = (w + 4 * t) * 8 + colq;
            *(unsigned*)&sOut[rowq * RC_ + col] = s0;
            *(unsigned*)&sOut[(rowq + 8) * RC_ + col] = s1;
        }
        __syncthreads();

        uint4* dst4 = (uint4*)&g_mh[(size_t)gt * 16 * RC_];
        const uint4* src4 = (const uint4*)sOut;
        for (int i = tid; i < 16 * RC_ / 8; i += 128)
            dst4[i] = src4[i];
        __syncthreads();
    }
}

// ---------------------------------------------------------------------------
// layer-2 edge pass incl. self-loop pseudo-edges: out[s,:] += v * m[o][r][:]
__global__ void k_l2e(const int* __restrict__ src, const int* __restrict__ dst,
                      const int* __restrict__ rel, float* __restrict__ out) {
    int idx = blockIdx.x * blockDim.x + threadIdx.x;
    if (idx >= (2 * E_ + N_) * 4) return;
    int q  = idx & 3;
    int e2 = idx >> 2;
    int s, o, r;
    float v;
    if (e2 < E_) {
        s = src[e2]; o = dst[e2]; r = rel[e2];
        v = 1.0f / (float)g_cnt[r * N_ + s];
    } else if (e2 < 2 * E_) {
        int e = e2 - E_;
        s = dst[e]; o = src[e]; r = rel[e] + R_;
        v = 1.0f / (float)g_cnt[r * N_ + s];
    } else {
        int n = e2 - 2 * E_;
        s = n; o = n; r = RT_ - 1; v = 1.0f;
    }
    const uint2 mw = *(const uint2*)&g_mh[(size_t)o * RC_ + r * 16 + q * 4];
    float2 f01 = __half22float2(*(const __half2*)&mw.x);
    float2 f23 = __half22float2(*(const __half2*)&mw.y);
    float* op = &out[s * C_ + q * 4];
    asm volatile("red.global.add.v4.f32 [%0], {%1, %2, %3, %4};"
                 :: "l"(op), "f"(v * f01.x), "f"(v * f01.y),
                    "f"(v * f23.x), "f"(v * f23.y)
                 : "memory");
}

// ---------------------------------------------------------------------------
extern "C" void kernel_launch(void* const* d_in, const int* in_sizes, int n_in,
                              void* d_out, int out_size) {
    const int*   src    = (const int*)d_in[0];
    const int*   dst    = (const int*)d_in[1];
    const int*   rel    = (const int*)d_in[2];
    const float* comps1 = (const float*)d_in[3];
    const float* bases1 = (const float*)d_in[4];
    const float* comps2 = (const float*)d_in[5];
    const float* bases2 = (const float*)d_in[6];
    const float* bias1  = (const float*)d_in[7];
    const float* bias2  = (const float*)d_in[8];
    float* out = (float*)d_out;

    static bool attr_set = false;
    if (!attr_set) {
        cudaFuncSetAttribute(k_w1t, cudaFuncAttributeMaxDynamicSharedMemorySize,
                             SMEM_W1);
        attr_set = true;
    }

    const int T = 256;
    k_pre   <<<(RT_ * N_ + T - 1) / T, T>>>(out, bias2, comps2, bases2);
    k_w1t   <<<WGB_ + CB2_, T, SMEM_W1>>>(comps1, bases1, src, dst, rel);
    k_l1    <<<(2 * E_ * 4 + T - 1) / T, T>>>(src, dst, rel);
    k_mgemm <<<(NTILES_ + NT_ - 1) / NT_, 128>>>(bias1);
    k_l2e   <<<((2 * E_ + N_) * 4 + T - 1) / T, T>>>(src, dst, rel, out);
}